// round 7
// baseline (speedup 1.0000x reference)
#include <cuda_runtime.h>

// ST-BIF IF neuron, T=16 scan. Persistent grid-stride version of the R6
// winner: 8 elems/chunk (2x float4, MLP_p1=2), block=128, ~10 CTAs/SM,
// each CTA walks multiple chunks to kill tail-wave and relaunch overhead.

#define T_STEPS 16
#define POS_MAX 7.0f
#define NEG_MIN (-8.0f)

__device__ __forceinline__ void step_elem(float& v, float rcp, float qth,
                                          float& q, float& a)
{
    q += v * rcp;                    // qth = 0.5 -> rcp = 2.0 exact
    bool sp = (q - 1.0f >= 0.0f) && (a < POS_MAX);
    bool ng = (q < 0.0f) && (a > NEG_MIN);
    float cur = sp ? 1.0f : (ng ? -1.0f : 0.0f);
    a += cur;
    q -= cur;
    v = cur * qth;                   // output overwrites input register
}

__global__ void __launch_bounds__(128) ifneuron_kernel(
    const float* __restrict__ x,
    const float* __restrict__ qth_ptr,
    float* __restrict__ out,
    int S)   // spatial size (B*N*D), multiple of 8
{
    const float qth = __ldg(qth_ptr);
    const float rcp = 1.0f / qth;

    const int stride = gridDim.x * blockDim.x * 8;   // elems per grid pass

    for (int idx = (blockIdx.x * blockDim.x + threadIdx.x) * 8;
         idx < S; idx += stride)
    {
        float q[8];
        float a[8];
        #pragma unroll
        for (int i = 0; i < 8; i++) { q[i] = 0.5f; a[i] = 0.0f; }

        #pragma unroll
        for (int t = 0; t < T_STEPS; t++) {
            const float* xp = x + (size_t)t * S + idx;
            float4 xa = __ldcs(reinterpret_cast<const float4*>(xp));
            float4 xb = __ldcs(reinterpret_cast<const float4*>(xp + 4));

            step_elem(xa.x, rcp, qth, q[0], a[0]);
            step_elem(xa.y, rcp, qth, q[1], a[1]);
            step_elem(xa.z, rcp, qth, q[2], a[2]);
            step_elem(xa.w, rcp, qth, q[3], a[3]);
            step_elem(xb.x, rcp, qth, q[4], a[4]);
            step_elem(xb.y, rcp, qth, q[5], a[5]);
            step_elem(xb.z, rcp, qth, q[6], a[6]);
            step_elem(xb.w, rcp, qth, q[7], a[7]);

            float* op = out + (size_t)t * S + idx;
            __stcs(reinterpret_cast<float4*>(op), xa);
            __stcs(reinterpret_cast<float4*>(op + 4), xb);
        }
    }
}

extern "C" void kernel_launch(void* const* d_in, const int* in_sizes, int n_in,
                              void* d_out, int out_size)
{
    const float* x   = (const float*)d_in[0];
    const float* qth = (const float*)d_in[1];
    float* out       = (float*)d_out;

    int total = in_sizes[0];          // T * S
    int S = total / T_STEPS;          // 9,633,792

    int block = 128;
    int grid = 152 * 10;              // ~10 CTAs/SM on GB300 (152 SMs)
    int max_grid = (S / 8 + block - 1) / block;
    if (grid > max_grid) grid = max_grid;

    ifneuron_kernel<<<grid, block>>>(x, qth, out, S);
}

// round 8
// speedup vs baseline: 1.1517x; 1.1517x over previous
#include <cuda_runtime.h>

// ST-BIF IF neuron, T=16 scan. R6 winner structure (8 elems/thread, 2x float4,
// block=128, one-shot CTAs) with write-through stores (__stwt) so the write
// stream does not allocate L2 lines against the read stream.

#define T_STEPS 16
#define POS_MAX 7.0f
#define NEG_MIN (-8.0f)

__device__ __forceinline__ void step_elem(float& v, float rcp, float qth,
                                          float& q, float& a)
{
    q += v * rcp;                    // qth = 0.5 -> rcp = 2.0 exact
    bool sp = (q - 1.0f >= 0.0f) && (a < POS_MAX);
    bool ng = (q < 0.0f) && (a > NEG_MIN);
    float cur = sp ? 1.0f : (ng ? -1.0f : 0.0f);
    a += cur;
    q -= cur;
    v = cur * qth;                   // output overwrites input register
}

__global__ void __launch_bounds__(128) ifneuron_kernel(
    const float* __restrict__ x,
    const float* __restrict__ qth_ptr,
    float* __restrict__ out,
    int S)   // spatial size (B*N*D), multiple of 8
{
    int idx = (blockIdx.x * blockDim.x + threadIdx.x) * 8;
    if (idx >= S) return;

    const float qth = __ldg(qth_ptr);
    const float rcp = 1.0f / qth;

    float q[8];
    float a[8];
    #pragma unroll
    for (int i = 0; i < 8; i++) { q[i] = 0.5f; a[i] = 0.0f; }

    #pragma unroll
    for (int t = 0; t < T_STEPS; t++) {
        const float* xp = x + (size_t)t * S + idx;
        float4 xa = __ldcs(reinterpret_cast<const float4*>(xp));
        float4 xb = __ldcs(reinterpret_cast<const float4*>(xp + 4));

        step_elem(xa.x, rcp, qth, q[0], a[0]);
        step_elem(xa.y, rcp, qth, q[1], a[1]);
        step_elem(xa.z, rcp, qth, q[2], a[2]);
        step_elem(xa.w, rcp, qth, q[3], a[3]);
        step_elem(xb.x, rcp, qth, q[4], a[4]);
        step_elem(xb.y, rcp, qth, q[5], a[5]);
        step_elem(xb.z, rcp, qth, q[6], a[6]);
        step_elem(xb.w, rcp, qth, q[7], a[7]);

        float* op = out + (size_t)t * S + idx;
        __stwt(reinterpret_cast<float4*>(op), xa);
        __stwt(reinterpret_cast<float4*>(op + 4), xb);
    }
}

extern "C" void kernel_launch(void* const* d_in, const int* in_sizes, int n_in,
                              void* d_out, int out_size)
{
    const float* x   = (const float*)d_in[0];
    const float* qth = (const float*)d_in[1];
    float* out       = (float*)d_out;

    int total = in_sizes[0];          // T * S
    int S = total / T_STEPS;          // 9,633,792
    int nthreads = S / 8;
    int block = 128;
    int grid = (nthreads + block - 1) / block;

    ifneuron_kernel<<<grid, block>>>(x, qth, out, S);
}

// round 9
// speedup vs baseline: 1.1787x; 1.0234x over previous
#include <cuda_runtime.h>

// ST-BIF IF neuron, T=16 scan. R6 winner body (8 elems/thread, 2x float4,
// __ldcs/__stcs, rcp-multiply, float acc) with block=64 to probe the last
// CTA-granularity step (128->64). Per-warp SASS identical to R6.

#define T_STEPS 16
#define POS_MAX 7.0f
#define NEG_MIN (-8.0f)

__device__ __forceinline__ void step_elem(float& v, float rcp, float qth,
                                          float& q, float& a)
{
    q += v * rcp;                    // qth = 0.5 -> rcp = 2.0 exact
    bool sp = (q - 1.0f >= 0.0f) && (a < POS_MAX);
    bool ng = (q < 0.0f) && (a > NEG_MIN);
    float cur = sp ? 1.0f : (ng ? -1.0f : 0.0f);
    a += cur;
    q -= cur;
    v = cur * qth;                   // output overwrites input register
}

__global__ void __launch_bounds__(64) ifneuron_kernel(
    const float* __restrict__ x,
    const float* __restrict__ qth_ptr,
    float* __restrict__ out,
    int S)   // spatial size (B*N*D), multiple of 8
{
    int idx = (blockIdx.x * blockDim.x + threadIdx.x) * 8;
    if (idx >= S) return;

    const float qth = __ldg(qth_ptr);
    const float rcp = 1.0f / qth;

    float q[8];
    float a[8];
    #pragma unroll
    for (int i = 0; i < 8; i++) { q[i] = 0.5f; a[i] = 0.0f; }

    #pragma unroll
    for (int t = 0; t < T_STEPS; t++) {
        const float* xp = x + (size_t)t * S + idx;
        float4 xa = __ldcs(reinterpret_cast<const float4*>(xp));
        float4 xb = __ldcs(reinterpret_cast<const float4*>(xp + 4));

        step_elem(xa.x, rcp, qth, q[0], a[0]);
        step_elem(xa.y, rcp, qth, q[1], a[1]);
        step_elem(xa.z, rcp, qth, q[2], a[2]);
        step_elem(xa.w, rcp, qth, q[3], a[3]);
        step_elem(xb.x, rcp, qth, q[4], a[4]);
        step_elem(xb.y, rcp, qth, q[5], a[5]);
        step_elem(xb.z, rcp, qth, q[6], a[6]);
        step_elem(xb.w, rcp, qth, q[7], a[7]);

        float* op = out + (size_t)t * S + idx;
        __stcs(reinterpret_cast<float4*>(op), xa);
        __stcs(reinterpret_cast<float4*>(op + 4), xb);
    }
}

extern "C" void kernel_launch(void* const* d_in, const int* in_sizes, int n_in,
                              void* d_out, int out_size)
{
    const float* x   = (const float*)d_in[0];
    const float* qth = (const float*)d_in[1];
    float* out       = (float*)d_out;

    int total = in_sizes[0];          // T * S
    int S = total / T_STEPS;          // 9,633,792
    int nthreads = S / 8;
    int block = 64;
    int grid = (nthreads + block - 1) / block;

    ifneuron_kernel<<<grid, block>>>(x, qth, out, S);
}